// round 1
// baseline (speedup 1.0000x reference)
#include <cuda_runtime.h>
#include <cuda_bf16.h>
#include <math.h>

// Problem constants
constexpr int CB  = 2;
constexpr int CS  = 2048;
constexpr int CD  = 1024;
constexpr int CH  = 16;
constexpr int CHD = 64;

// Scratch (allocation-free rule: static __device__ arrays)
__device__ __align__(256) float g_q[CB * CS * CD];
__device__ __align__(256) float g_k[CB * CS * CD];
__device__ __align__(256) float g_v[CB * CS * CD];
__device__ __align__(256) float g_vals[CB * CS * CD];

// ---------------------------------------------------------------------------
// Tiled SGEMM: C[M,N] = A[M,K] * W[K,N], fp32, all dims multiples of 64/16.
// Block tile 64x64, K-step 16, 256 threads, 4x4 micro-tile per thread.
// ---------------------------------------------------------------------------
__global__ __launch_bounds__(256) void sgemm64(const float* __restrict__ A,
                                               const float* __restrict__ W,
                                               float* __restrict__ C,
                                               int M, int N, int K) {
    __shared__ float As[16][64];
    __shared__ float Bs[16][64];

    const int t  = threadIdx.x;
    const int tx = t & 15, ty = t >> 4;
    const int n0 = blockIdx.x * 64, m0 = blockIdx.y * 64;

    const int la_m = t >> 2, la_k = (t & 3) * 4;
    const int lb_k = t >> 4, lb_n = (t & 15) * 4;

    float acc[4][4];
#pragma unroll
    for (int i = 0; i < 4; ++i)
#pragma unroll
        for (int j = 0; j < 4; ++j) acc[i][j] = 0.f;

    for (int k0 = 0; k0 < K; k0 += 16) {
        float4 av = *(const float4*)&A[(size_t)(m0 + la_m) * K + k0 + la_k];
        As[la_k + 0][la_m] = av.x;
        As[la_k + 1][la_m] = av.y;
        As[la_k + 2][la_m] = av.z;
        As[la_k + 3][la_m] = av.w;
        *(float4*)&Bs[lb_k][lb_n] =
            *(const float4*)&W[(size_t)(k0 + lb_k) * N + n0 + lb_n];
        __syncthreads();

#pragma unroll
        for (int kk = 0; kk < 16; ++kk) {
            float4 a4 = *(const float4*)&As[kk][ty * 4];
            float4 b4 = *(const float4*)&Bs[kk][tx * 4];
            float a[4] = {a4.x, a4.y, a4.z, a4.w};
            float b[4] = {b4.x, b4.y, b4.z, b4.w};
#pragma unroll
            for (int i = 0; i < 4; ++i)
#pragma unroll
                for (int j = 0; j < 4; ++j) acc[i][j] += a[i] * b[j];
        }
        __syncthreads();
    }

#pragma unroll
    for (int i = 0; i < 4; ++i) {
        float4 o = make_float4(acc[i][0], acc[i][1], acc[i][2], acc[i][3]);
        *(float4*)&C[(size_t)(m0 + ty * 4 + i) * N + n0 + tx * 4] = o;
    }
}

// ---------------------------------------------------------------------------
// RoPE (bf16 cos/sin tables, matching reference) + RMSNorm, in place.
// One warp per (b, s, h) head vector of 64 floats.
// ---------------------------------------------------------------------------
__global__ __launch_bounds__(256) void rope_rms_kernel(float* __restrict__ x) {
    const int gt   = blockIdx.x * blockDim.x + threadIdx.x;
    const int gw   = gt >> 5;
    const int lane = gt & 31;
    if (gw >= CB * CS * CH) return;

    const int sPos = (gw / CH) % CS;
    float* p = x + (size_t)gw * CHD;

    const float x1 = p[lane];
    const float x2 = p[lane + 32];

    // freqs = ROPE_BASE ** (2*lane / 64); gamma = pos * (1/freqs); tables in bf16
    const float ex = (float)(2 * lane) * (1.0f / 64.0f);
    const float fr = powf(100000.0f, ex);
    const float g  = (float)sPos * (1.0f / fr);
    const float c  = __bfloat162float(__float2bfloat16(cosf(g)));
    const float sn = __bfloat162float(__float2bfloat16(sinf(g)));

    const float y1 = x1 * c + x2 * sn;
    const float y2 = -x1 * sn + x2 * c;

    float ss = y1 * y1 + y2 * y2;
#pragma unroll
    for (int o = 16; o > 0; o >>= 1) ss += __shfl_xor_sync(0xffffffffu, ss, o);

    const float rms = sqrtf(ss * (1.0f / 64.0f) + 1e-9f);
    const float ir  = 1.0f / rms;
    p[lane]      = y1 * ir;
    p[lane + 32] = y2 * ir;
}

// ---------------------------------------------------------------------------
// Causal flash attention, fp32. Layouts: q,k,v,o all [B, S, H, HD].
// Block: 64 q-rows for one (b,h); K/V tiles of 32 rows; 256 threads.
// ---------------------------------------------------------------------------
__global__ __launch_bounds__(256) void flash_attn_kernel(
    const float* __restrict__ q, const float* __restrict__ k,
    const float* __restrict__ v, float* __restrict__ o) {
    __shared__ float Qs[64][65];
    __shared__ float Ks[32][65];
    __shared__ float Vs[32][68];
    __shared__ float Ps[64][33];

    const int t  = threadIdx.x;
    const int q0 = blockIdx.x * 64;
    const int bh = blockIdx.y;
    const int b = bh >> 4, h = bh & 15;
    const size_t base = ((size_t)b * CS * CH + h) * CHD;
    const int rs = CH * CHD;  // 1024

    for (int i = t; i < 64 * 64; i += 256) {
        int r = i >> 6, d = i & 63;
        Qs[r][d] = q[base + (size_t)(q0 + r) * rs + d];
    }

    float acc[16];
#pragma unroll
    for (int j = 0; j < 16; ++j) acc[j] = 0.f;
    float mrow = -1e30f, lrow = 0.f;

    const int r = t >> 2, dl = t & 3;      // softmax/PV mapping (warp-private rows)
    const int qg = t >> 4, kg = t & 15;    // score mapping (4q x 2k micro)
    __syncthreads();

    const int nkt = (q0 >> 5) + 2;
    for (int kt = 0; kt < nkt; ++kt) {
        const int k0 = kt << 5;
        for (int i = t; i < 32 * 64; i += 256) {
            int rr = i >> 6, d = i & 63;
            size_t gi = base + (size_t)(k0 + rr) * rs + d;
            Ks[rr][d] = k[gi];
            Vs[rr][d] = v[gi];
        }
        __syncthreads();

        // scores: rows 4*qg..+3, cols 2*kg..+1
        float sc00 = 0.f, sc01 = 0.f, sc10 = 0.f, sc11 = 0.f;
        float sc20 = 0.f, sc21 = 0.f, sc30 = 0.f, sc31 = 0.f;
#pragma unroll 8
        for (int d = 0; d < 64; ++d) {
            float a0 = Qs[qg * 4 + 0][d];
            float a1 = Qs[qg * 4 + 1][d];
            float a2 = Qs[qg * 4 + 2][d];
            float a3 = Qs[qg * 4 + 3][d];
            float b0 = Ks[kg * 2 + 0][d];
            float b1 = Ks[kg * 2 + 1][d];
            sc00 += a0 * b0; sc01 += a0 * b1;
            sc10 += a1 * b0; sc11 += a1 * b1;
            sc20 += a2 * b0; sc21 += a2 * b1;
            sc30 += a3 * b0; sc31 += a3 * b1;
        }

        const bool needmask = (k0 + 31 > q0);
        float scm[4][2] = {{sc00, sc01}, {sc10, sc11}, {sc20, sc21}, {sc30, sc31}};
#pragma unroll
        for (int i = 0; i < 4; ++i)
#pragma unroll
            for (int j = 0; j < 2; ++j) {
                int qp = q0 + qg * 4 + i, kp = k0 + kg * 2 + j;
                float sv = scm[i][j] * 0.125f;
                if (needmask && kp > qp) sv = -1e9f;
                Ps[qg * 4 + i][kg * 2 + j] = sv;
            }
        // Ps rows 8w..8w+7 are produced and consumed entirely by warp w
        __syncwarp();

        float tm = -1e30f;
#pragma unroll
        for (int kk = 0; kk < 32; ++kk) tm = fmaxf(tm, Ps[r][kk]);
        const float mnew  = fmaxf(mrow, tm);
        const float alpha = __expf(mrow - mnew);
        float psum = 0.f;
#pragma unroll
        for (int i = 0; i < 8; ++i) {
            int kk = dl + 4 * i;
            float p = __expf(Ps[r][kk] - mnew);
            Ps[r][kk] = p;
            psum += p;
        }
        psum += __shfl_xor_sync(0xffffffffu, psum, 1);
        psum += __shfl_xor_sync(0xffffffffu, psum, 2);
        lrow = lrow * alpha + psum;
        mrow = mnew;
#pragma unroll
        for (int j = 0; j < 16; ++j) acc[j] *= alpha;
        __syncwarp();

        // PV: thread owns dims [dl*16, dl*16+16)
        for (int kk = 0; kk < 32; ++kk) {
            const float p = Ps[r][kk];
            const float4 v0 = *(const float4*)&Vs[kk][dl * 16 + 0];
            const float4 v1 = *(const float4*)&Vs[kk][dl * 16 + 4];
            const float4 v2 = *(const float4*)&Vs[kk][dl * 16 + 8];
            const float4 v3 = *(const float4*)&Vs[kk][dl * 16 + 12];
            acc[0]  += p * v0.x; acc[1]  += p * v0.y; acc[2]  += p * v0.z; acc[3]  += p * v0.w;
            acc[4]  += p * v1.x; acc[5]  += p * v1.y; acc[6]  += p * v1.z; acc[7]  += p * v1.w;
            acc[8]  += p * v2.x; acc[9]  += p * v2.y; acc[10] += p * v2.z; acc[11] += p * v2.w;
            acc[12] += p * v3.x; acc[13] += p * v3.y; acc[14] += p * v3.z; acc[15] += p * v3.w;
        }
        __syncthreads();
    }

    const float invl = 1.0f / lrow;
    const size_t ob = base + (size_t)(q0 + r) * rs + dl * 16;
#pragma unroll
    for (int jj = 0; jj < 4; ++jj) {
        float4 w4 = make_float4(acc[4 * jj + 0] * invl, acc[4 * jj + 1] * invl,
                                acc[4 * jj + 2] * invl, acc[4 * jj + 3] * invl);
        *(float4*)&o[ob + 4 * jj] = w4;
    }
}

// ---------------------------------------------------------------------------
// Launch
// ---------------------------------------------------------------------------
extern "C" void kernel_launch(void* const* d_in, const int* in_sizes, int n_in,
                              void* d_out, int out_size) {
    (void)in_sizes; (void)n_in; (void)out_size;
    const float* Q  = (const float*)d_in[0];
    const float* K  = (const float*)d_in[1];
    const float* V  = (const float*)d_in[2];
    // d_in[3] = mask (causal tril) — implied by kernel logic, unused
    const float* Wq = (const float*)d_in[4];
    const float* Wk = (const float*)d_in[5];
    const float* Wv = (const float*)d_in[6];
    const float* Wo = (const float*)d_in[7];
    float* out = (float*)d_out;

    float *gq, *gk, *gv, *gvals;
    cudaGetSymbolAddress((void**)&gq, g_q);
    cudaGetSymbolAddress((void**)&gk, g_k);
    cudaGetSymbolAddress((void**)&gv, g_v);
    cudaGetSymbolAddress((void**)&gvals, g_vals);

    const int M = CB * CS;               // 4096
    dim3 ggrid(CD / 64, M / 64);         // (16, 64)

    sgemm64<<<ggrid, 256>>>(Q, Wq, gq, M, CD, CD);
    sgemm64<<<ggrid, 256>>>(K, Wk, gk, M, CD, CD);
    sgemm64<<<ggrid, 256>>>(V, Wv, gv, M, CD, CD);

    const int nwarps = CB * CS * CH;     // 65536
    dim3 rgrid(nwarps / 8);              // 8 warps per 256-thread block
    rope_rms_kernel<<<rgrid, 256>>>(gq);
    rope_rms_kernel<<<rgrid, 256>>>(gk);

    dim3 agrid(CS / 64, CB * CH);        // (32, 32)
    flash_attn_kernel<<<agrid, 256>>>(gq, gk, gv, gvals);

    sgemm64<<<ggrid, 256>>>(gvals, Wo, out, M, CD, CD);
}

// round 2
// speedup vs baseline: 1.2781x; 1.2781x over previous
#include <cuda_runtime.h>
#include <cuda_bf16.h>
#include <math.h>
#include <stdint.h>

// Problem constants
constexpr int CB  = 2;
constexpr int CS  = 2048;
constexpr int CD  = 1024;
constexpr int CH  = 16;
constexpr int CHD = 64;

// Scratch (allocation-free rule: static __device__ arrays)
__device__ __align__(256) float g_q[CB * CS * CD];
__device__ __align__(256) float g_k[CB * CS * CD];
__device__ __align__(256) float g_v[CB * CS * CD];
__device__ __align__(256) float g_vals[CB * CS * CD];

// ---------------------------------------------------------------------------
// TF32 helpers
// ---------------------------------------------------------------------------
__device__ __forceinline__ uint32_t f2tf32(float x) {
    uint32_t u;
    asm("cvt.rna.tf32.f32 %0, %1;" : "=r"(u) : "f"(x));
    return u;
}

__device__ __forceinline__ void mma_tf32(float c[4], const uint32_t a[4],
                                         const uint32_t b[2]) {
    asm volatile(
        "mma.sync.aligned.m16n8k8.row.col.f32.tf32.tf32.f32 "
        "{%0,%1,%2,%3}, {%4,%5,%6,%7}, {%8,%9}, {%0,%1,%2,%3};"
        : "+f"(c[0]), "+f"(c[1]), "+f"(c[2]), "+f"(c[3])
        : "r"(a[0]), "r"(a[1]), "r"(a[2]), "r"(a[3]), "r"(b[0]), "r"(b[1]));
}

// ---------------------------------------------------------------------------
// TF32 tensor-core GEMM: C[M,N] = A[M,K] * W[K,N].
// Block tile 128x128, BK=16, 256 threads (8 warps, 2x4 warp grid, 64x32 each).
// ---------------------------------------------------------------------------
constexpr int BM = 128, BN = 128, BKt = 16;

__global__ __launch_bounds__(256) void sgemm_tf32(const float* __restrict__ A,
                                                  const float* __restrict__ W,
                                                  float* __restrict__ C,
                                                  int M, int N, int K) {
    __shared__ uint32_t As[BKt][BM + 4];
    __shared__ uint32_t Bs[BKt][BN + 4];

    const int t    = threadIdx.x;
    const int lane = t & 31;
    const int warp = t >> 5;
    const int wm   = warp & 1;   // 0..1
    const int wn   = warp >> 1;  // 0..3
    const int gid  = lane >> 2;  // 0..7
    const int tg   = lane & 3;   // 0..3

    const int m0b = blockIdx.y * BM;
    const int n0b = blockIdx.x * BN;

    // global-load mapping
    const int arow = t >> 2;        // 0..63
    const int acol = (t & 3) * 4;   // 0..12
    const int brow = t >> 4;        // 0..15
    const int bcol = (t & 15) * 4;  // 0..60

    float4 aRegs[2], bRegs[2];

    float c[4][4][4];
#pragma unroll
    for (int mt = 0; mt < 4; ++mt)
#pragma unroll
        for (int nt = 0; nt < 4; ++nt)
#pragma unroll
            for (int i = 0; i < 4; ++i) c[mt][nt][i] = 0.f;

    // prologue: tile 0
    {
        aRegs[0] = *(const float4*)&A[(size_t)(m0b + arow) * K + acol];
        aRegs[1] = *(const float4*)&A[(size_t)(m0b + arow + 64) * K + acol];
        bRegs[0] = *(const float4*)&W[(size_t)brow * N + n0b + bcol];
        bRegs[1] = *(const float4*)&W[(size_t)brow * N + n0b + bcol + 64];
#pragma unroll
        for (int i = 0; i < 2; ++i) {
            const float* f = (const float*)&aRegs[i];
#pragma unroll
            for (int j = 0; j < 4; ++j) As[acol + j][arow + i * 64] = f2tf32(f[j]);
        }
#pragma unroll
        for (int i = 0; i < 2; ++i) {
            const float* f = (const float*)&bRegs[i];
#pragma unroll
            for (int j = 0; j < 4; ++j) Bs[brow][bcol + i * 64 + j] = f2tf32(f[j]);
        }
    }
    __syncthreads();

    for (int k0 = 0; k0 < K; k0 += BKt) {
        const bool has_next = (k0 + BKt < K);
        if (has_next) {
            const int kn = k0 + BKt;
            aRegs[0] = *(const float4*)&A[(size_t)(m0b + arow) * K + kn + acol];
            aRegs[1] = *(const float4*)&A[(size_t)(m0b + arow + 64) * K + kn + acol];
            bRegs[0] = *(const float4*)&W[(size_t)(kn + brow) * N + n0b + bcol];
            bRegs[1] = *(const float4*)&W[(size_t)(kn + brow) * N + n0b + bcol + 64];
        }

#pragma unroll
        for (int kk = 0; kk < BKt; kk += 8) {
            uint32_t af[4][4], bf[4][2];
#pragma unroll
            for (int mt = 0; mt < 4; ++mt) {
                const int mm = wm * 64 + mt * 16 + gid;
                af[mt][0] = As[kk + tg][mm];
                af[mt][1] = As[kk + tg][mm + 8];
                af[mt][2] = As[kk + tg + 4][mm];
                af[mt][3] = As[kk + tg + 4][mm + 8];
            }
#pragma unroll
            for (int nt = 0; nt < 4; ++nt) {
                const int nn = wn * 32 + nt * 8 + gid;
                bf[nt][0] = Bs[kk + tg][nn];
                bf[nt][1] = Bs[kk + tg + 4][nn];
            }
#pragma unroll
            for (int mt = 0; mt < 4; ++mt)
#pragma unroll
                for (int nt = 0; nt < 4; ++nt) mma_tf32(c[mt][nt], af[mt], bf[nt]);
        }

        if (has_next) {
            __syncthreads();
#pragma unroll
            for (int i = 0; i < 2; ++i) {
                const float* f = (const float*)&aRegs[i];
#pragma unroll
                for (int j = 0; j < 4; ++j) As[acol + j][arow + i * 64] = f2tf32(f[j]);
            }
#pragma unroll
            for (int i = 0; i < 2; ++i) {
                const float* f = (const float*)&bRegs[i];
#pragma unroll
                for (int j = 0; j < 4; ++j) Bs[brow][bcol + i * 64 + j] = f2tf32(f[j]);
            }
            __syncthreads();
        }
    }

    // epilogue
#pragma unroll
    for (int mt = 0; mt < 4; ++mt) {
        const int r0 = m0b + wm * 64 + mt * 16 + gid;
#pragma unroll
        for (int nt = 0; nt < 4; ++nt) {
            const int cc = n0b + wn * 32 + nt * 8 + tg * 2;
            *(float2*)&C[(size_t)r0 * N + cc]       = make_float2(c[mt][nt][0], c[mt][nt][1]);
            *(float2*)&C[(size_t)(r0 + 8) * N + cc] = make_float2(c[mt][nt][2], c[mt][nt][3]);
        }
    }
}

// ---------------------------------------------------------------------------
// RoPE (bf16 cos/sin tables, matching reference) + RMSNorm, in place.
// One warp per (b, s, h) head vector of 64 floats.
// ---------------------------------------------------------------------------
__global__ __launch_bounds__(256) void rope_rms_kernel(float* __restrict__ x) {
    const int gt   = blockIdx.x * blockDim.x + threadIdx.x;
    const int gw   = gt >> 5;
    const int lane = gt & 31;
    if (gw >= CB * CS * CH) return;

    const int sPos = (gw / CH) % CS;
    float* p = x + (size_t)gw * CHD;

    const float x1 = p[lane];
    const float x2 = p[lane + 32];

    const float ex = (float)(2 * lane) * (1.0f / 64.0f);
    const float fr = powf(100000.0f, ex);
    const float g  = (float)sPos * (1.0f / fr);
    const float cc = __bfloat162float(__float2bfloat16(cosf(g)));
    const float sn = __bfloat162float(__float2bfloat16(sinf(g)));

    const float y1 = x1 * cc + x2 * sn;
    const float y2 = -x1 * sn + x2 * cc;

    float ss = y1 * y1 + y2 * y2;
#pragma unroll
    for (int o = 16; o > 0; o >>= 1) ss += __shfl_xor_sync(0xffffffffu, ss, o);

    const float rms = sqrtf(ss * (1.0f / 64.0f) + 1e-9f);
    const float ir  = 1.0f / rms;
    p[lane]      = y1 * ir;
    p[lane + 32] = y2 * ir;
}

// ---------------------------------------------------------------------------
// Causal flash attention, fp32. Layouts: q,k,v,o all [B, S, H, HD].
// Block: 64 q-rows for one (b,h); K/V tiles of 32 rows; 256 threads.
// ---------------------------------------------------------------------------
__global__ __launch_bounds__(256) void flash_attn_kernel(
    const float* __restrict__ q, const float* __restrict__ k,
    const float* __restrict__ v, float* __restrict__ o) {
    __shared__ float Qs[64][65];
    __shared__ float Ks[32][65];
    __shared__ float Vs[32][68];
    __shared__ float Ps[64][33];

    const int t  = threadIdx.x;
    const int q0 = blockIdx.x * 64;
    const int bh = blockIdx.y;
    const int b = bh >> 4, h = bh & 15;
    const size_t base = ((size_t)b * CS * CH + h) * CHD;
    const int rs = CH * CHD;  // 1024

    for (int i = t; i < 64 * 64; i += 256) {
        int r = i >> 6, d = i & 63;
        Qs[r][d] = q[base + (size_t)(q0 + r) * rs + d];
    }

    float acc[16];
#pragma unroll
    for (int j = 0; j < 16; ++j) acc[j] = 0.f;
    float mrow = -1e30f, lrow = 0.f;

    const int r = t >> 2, dl = t & 3;
    const int qg = t >> 4, kg = t & 15;
    __syncthreads();

    const int nkt = (q0 >> 5) + 2;
    for (int kt = 0; kt < nkt; ++kt) {
        const int k0 = kt << 5;
        for (int i = t; i < 32 * 64; i += 256) {
            int rr = i >> 6, d = i & 63;
            size_t gi = base + (size_t)(k0 + rr) * rs + d;
            Ks[rr][d] = k[gi];
            Vs[rr][d] = v[gi];
        }
        __syncthreads();

        float sc00 = 0.f, sc01 = 0.f, sc10 = 0.f, sc11 = 0.f;
        float sc20 = 0.f, sc21 = 0.f, sc30 = 0.f, sc31 = 0.f;
#pragma unroll 8
        for (int d = 0; d < 64; ++d) {
            float a0 = Qs[qg * 4 + 0][d];
            float a1 = Qs[qg * 4 + 1][d];
            float a2 = Qs[qg * 4 + 2][d];
            float a3 = Qs[qg * 4 + 3][d];
            float b0 = Ks[kg * 2 + 0][d];
            float b1 = Ks[kg * 2 + 1][d];
            sc00 += a0 * b0; sc01 += a0 * b1;
            sc10 += a1 * b0; sc11 += a1 * b1;
            sc20 += a2 * b0; sc21 += a2 * b1;
            sc30 += a3 * b0; sc31 += a3 * b1;
        }

        const bool needmask = (k0 + 31 > q0);
        float scm[4][2] = {{sc00, sc01}, {sc10, sc11}, {sc20, sc21}, {sc30, sc31}};
#pragma unroll
        for (int i = 0; i < 4; ++i)
#pragma unroll
            for (int j = 0; j < 2; ++j) {
                int qp = q0 + qg * 4 + i, kp = k0 + kg * 2 + j;
                float sv = scm[i][j] * 0.125f;
                if (needmask && kp > qp) sv = -1e9f;
                Ps[qg * 4 + i][kg * 2 + j] = sv;
            }
        __syncwarp();

        float tm = -1e30f;
#pragma unroll
        for (int kk = 0; kk < 32; ++kk) tm = fmaxf(tm, Ps[r][kk]);
        const float mnew  = fmaxf(mrow, tm);
        const float alpha = __expf(mrow - mnew);
        float psum = 0.f;
#pragma unroll
        for (int i = 0; i < 8; ++i) {
            int kk = dl + 4 * i;
            float p = __expf(Ps[r][kk] - mnew);
            Ps[r][kk] = p;
            psum += p;
        }
        psum += __shfl_xor_sync(0xffffffffu, psum, 1);
        psum += __shfl_xor_sync(0xffffffffu, psum, 2);
        lrow = lrow * alpha + psum;
        mrow = mnew;
#pragma unroll
        for (int j = 0; j < 16; ++j) acc[j] *= alpha;
        __syncwarp();

        for (int kk = 0; kk < 32; ++kk) {
            const float p = Ps[r][kk];
            const float4 v0 = *(const float4*)&Vs[kk][dl * 16 + 0];
            const float4 v1 = *(const float4*)&Vs[kk][dl * 16 + 4];
            const float4 v2 = *(const float4*)&Vs[kk][dl * 16 + 8];
            const float4 v3 = *(const float4*)&Vs[kk][dl * 16 + 12];
            acc[0]  += p * v0.x; acc[1]  += p * v0.y; acc[2]  += p * v0.z; acc[3]  += p * v0.w;
            acc[4]  += p * v1.x; acc[5]  += p * v1.y; acc[6]  += p * v1.z; acc[7]  += p * v1.w;
            acc[8]  += p * v2.x; acc[9]  += p * v2.y; acc[10] += p * v2.z; acc[11] += p * v2.w;
            acc[12] += p * v3.x; acc[13] += p * v3.y; acc[14] += p * v3.z; acc[15] += p * v3.w;
        }
        __syncthreads();
    }

    const float invl = 1.0f / lrow;
    const size_t ob = base + (size_t)(q0 + r) * rs + dl * 16;
#pragma unroll
    for (int jj = 0; jj < 4; ++jj) {
        float4 w4 = make_float4(acc[4 * jj + 0] * invl, acc[4 * jj + 1] * invl,
                                acc[4 * jj + 2] * invl, acc[4 * jj + 3] * invl);
        *(float4*)&o[ob + 4 * jj] = w4;
    }
}

// ---------------------------------------------------------------------------
// Launch
// ---------------------------------------------------------------------------
extern "C" void kernel_launch(void* const* d_in, const int* in_sizes, int n_in,
                              void* d_out, int out_size) {
    (void)in_sizes; (void)n_in; (void)out_size;
    const float* Q  = (const float*)d_in[0];
    const float* K  = (const float*)d_in[1];
    const float* V  = (const float*)d_in[2];
    const float* Wq = (const float*)d_in[4];
    const float* Wk = (const float*)d_in[5];
    const float* Wv = (const float*)d_in[6];
    const float* Wo = (const float*)d_in[7];
    float* out = (float*)d_out;

    float *gq, *gk, *gv, *gvals;
    cudaGetSymbolAddress((void**)&gq, g_q);
    cudaGetSymbolAddress((void**)&gk, g_k);
    cudaGetSymbolAddress((void**)&gv, g_v);
    cudaGetSymbolAddress((void**)&gvals, g_vals);

    const int M = CB * CS;               // 4096
    dim3 ggrid(CD / BN, M / BM);         // (8, 32)

    sgemm_tf32<<<ggrid, 256>>>(Q, Wq, gq, M, CD, CD);
    sgemm_tf32<<<ggrid, 256>>>(K, Wk, gk, M, CD, CD);
    sgemm_tf32<<<ggrid, 256>>>(V, Wv, gv, M, CD, CD);

    const int nwarps = CB * CS * CH;     // 65536
    dim3 rgrid(nwarps / 8);
    rope_rms_kernel<<<rgrid, 256>>>(gq);
    rope_rms_kernel<<<rgrid, 256>>>(gk);

    dim3 agrid(CS / 64, CB * CH);        // (32, 32)
    flash_attn_kernel<<<agrid, 256>>>(gq, gk, gv, gvals);

    sgemm_tf32<<<ggrid, 256>>>(gvals, Wo, out, M, CD, CD);
}

// round 3
// speedup vs baseline: 4.2601x; 3.3332x over previous
#include <cuda_runtime.h>
#include <cuda_bf16.h>
#include <math.h>
#include <stdint.h>

// Problem constants
constexpr int CB  = 2;
constexpr int CS  = 2048;
constexpr int CD  = 1024;
constexpr int CH  = 16;
constexpr int CHD = 64;

// Scratch (allocation-free rule: static __device__ arrays)
__device__ __align__(256) float g_q[CB * CS * CD];
__device__ __align__(256) float g_k[CB * CS * CD];
__device__ __align__(256) float g_v[CB * CS * CD];
__device__ __align__(256) float g_vals[CB * CS * CD];

// ---------------------------------------------------------------------------
// TF32 helpers
// ---------------------------------------------------------------------------
__device__ __forceinline__ uint32_t f2tf32(float x) {
    uint32_t u;
    asm("cvt.rna.tf32.f32 %0, %1;" : "=r"(u) : "f"(x));
    return u;
}

__device__ __forceinline__ void mma_tf32(float c[4], const uint32_t a[4],
                                         const uint32_t b[2]) {
    asm volatile(
        "mma.sync.aligned.m16n8k8.row.col.f32.tf32.tf32.f32 "
        "{%0,%1,%2,%3}, {%4,%5,%6,%7}, {%8,%9}, {%0,%1,%2,%3};"
        : "+f"(c[0]), "+f"(c[1]), "+f"(c[2]), "+f"(c[3])
        : "r"(a[0]), "r"(a[1]), "r"(a[2]), "r"(a[3]), "r"(b[0]), "r"(b[1]));
}

// ---------------------------------------------------------------------------
// TF32 tensor-core GEMM: C[M,N] = A[M,K] * W[K,N].
// Block tile 128x128, BK=16, 256 threads (8 warps, 2x4 warp grid, 64x32 each).
// ---------------------------------------------------------------------------
constexpr int BM = 128, BN = 128, BKt = 16;

__global__ __launch_bounds__(256) void sgemm_tf32(const float* __restrict__ A,
                                                  const float* __restrict__ W,
                                                  float* __restrict__ C,
                                                  int M, int N, int K) {
    __shared__ uint32_t As[BKt][BM + 4];
    __shared__ uint32_t Bs[BKt][BN + 4];

    const int t    = threadIdx.x;
    const int lane = t & 31;
    const int warp = t >> 5;
    const int wm   = warp & 1;   // 0..1
    const int wn   = warp >> 1;  // 0..3
    const int gid  = lane >> 2;  // 0..7
    const int tg   = lane & 3;   // 0..3

    const int m0b = blockIdx.y * BM;
    const int n0b = blockIdx.x * BN;

    const int arow = t >> 2;        // 0..63
    const int acol = (t & 3) * 4;   // 0..12
    const int brow = t >> 4;        // 0..15
    const int bcol = (t & 15) * 4;  // 0..60

    float4 aRegs[2], bRegs[2];

    float c[4][4][4];
#pragma unroll
    for (int mt = 0; mt < 4; ++mt)
#pragma unroll
        for (int nt = 0; nt < 4; ++nt)
#pragma unroll
            for (int i = 0; i < 4; ++i) c[mt][nt][i] = 0.f;

    {
        aRegs[0] = *(const float4*)&A[(size_t)(m0b + arow) * K + acol];
        aRegs[1] = *(const float4*)&A[(size_t)(m0b + arow + 64) * K + acol];
        bRegs[0] = *(const float4*)&W[(size_t)brow * N + n0b + bcol];
        bRegs[1] = *(const float4*)&W[(size_t)brow * N + n0b + bcol + 64];
#pragma unroll
        for (int i = 0; i < 2; ++i) {
            const float* f = (const float*)&aRegs[i];
#pragma unroll
            for (int j = 0; j < 4; ++j) As[acol + j][arow + i * 64] = f2tf32(f[j]);
        }
#pragma unroll
        for (int i = 0; i < 2; ++i) {
            const float* f = (const float*)&bRegs[i];
#pragma unroll
            for (int j = 0; j < 4; ++j) Bs[brow][bcol + i * 64 + j] = f2tf32(f[j]);
        }
    }
    __syncthreads();

    for (int k0 = 0; k0 < K; k0 += BKt) {
        const bool has_next = (k0 + BKt < K);
        if (has_next) {
            const int kn = k0 + BKt;
            aRegs[0] = *(const float4*)&A[(size_t)(m0b + arow) * K + kn + acol];
            aRegs[1] = *(const float4*)&A[(size_t)(m0b + arow + 64) * K + kn + acol];
            bRegs[0] = *(const float4*)&W[(size_t)(kn + brow) * N + n0b + bcol];
            bRegs[1] = *(const float4*)&W[(size_t)(kn + brow) * N + n0b + bcol + 64];
        }

#pragma unroll
        for (int kk = 0; kk < BKt; kk += 8) {
            uint32_t af[4][4], bf[4][2];
#pragma unroll
            for (int mt = 0; mt < 4; ++mt) {
                const int mm = wm * 64 + mt * 16 + gid;
                af[mt][0] = As[kk + tg][mm];
                af[mt][1] = As[kk + tg][mm + 8];
                af[mt][2] = As[kk + tg + 4][mm];
                af[mt][3] = As[kk + tg + 4][mm + 8];
            }
#pragma unroll
            for (int nt = 0; nt < 4; ++nt) {
                const int nn = wn * 32 + nt * 8 + gid;
                bf[nt][0] = Bs[kk + tg][nn];
                bf[nt][1] = Bs[kk + tg + 4][nn];
            }
#pragma unroll
            for (int mt = 0; mt < 4; ++mt)
#pragma unroll
                for (int nt = 0; nt < 4; ++nt) mma_tf32(c[mt][nt], af[mt], bf[nt]);
        }

        if (has_next) {
            __syncthreads();
#pragma unroll
            for (int i = 0; i < 2; ++i) {
                const float* f = (const float*)&aRegs[i];
#pragma unroll
                for (int j = 0; j < 4; ++j) As[acol + j][arow + i * 64] = f2tf32(f[j]);
            }
#pragma unroll
            for (int i = 0; i < 2; ++i) {
                const float* f = (const float*)&bRegs[i];
#pragma unroll
                for (int j = 0; j < 4; ++j) Bs[brow][bcol + i * 64 + j] = f2tf32(f[j]);
            }
            __syncthreads();
        }
    }

#pragma unroll
    for (int mt = 0; mt < 4; ++mt) {
        const int r0 = m0b + wm * 64 + mt * 16 + gid;
#pragma unroll
        for (int nt = 0; nt < 4; ++nt) {
            const int cc = n0b + wn * 32 + nt * 8 + tg * 2;
            *(float2*)&C[(size_t)r0 * N + cc]       = make_float2(c[mt][nt][0], c[mt][nt][1]);
            *(float2*)&C[(size_t)(r0 + 8) * N + cc] = make_float2(c[mt][nt][2], c[mt][nt][3]);
        }
    }
}

// ---------------------------------------------------------------------------
// RoPE (bf16 cos/sin tables, matching reference) + RMSNorm, in place.
// ---------------------------------------------------------------------------
__global__ __launch_bounds__(256) void rope_rms_kernel(float* __restrict__ x) {
    const int gt   = blockIdx.x * blockDim.x + threadIdx.x;
    const int gw   = gt >> 5;
    const int lane = gt & 31;
    if (gw >= CB * CS * CH) return;

    const int sPos = (gw / CH) % CS;
    float* p = x + (size_t)gw * CHD;

    const float x1 = p[lane];
    const float x2 = p[lane + 32];

    const float ex = (float)(2 * lane) * (1.0f / 64.0f);
    const float fr = powf(100000.0f, ex);
    const float g  = (float)sPos * (1.0f / fr);
    const float cc = __bfloat162float(__float2bfloat16(cosf(g)));
    const float sn = __bfloat162float(__float2bfloat16(sinf(g)));

    const float y1 = x1 * cc + x2 * sn;
    const float y2 = -x1 * sn + x2 * cc;

    float ss = y1 * y1 + y2 * y2;
#pragma unroll
    for (int o = 16; o > 0; o >>= 1) ss += __shfl_xor_sync(0xffffffffu, ss, o);

    const float rms = sqrtf(ss * (1.0f / 64.0f) + 1e-9f);
    const float ir  = 1.0f / rms;
    p[lane]      = y1 * ir;
    p[lane + 32] = y2 * ir;
}

// ---------------------------------------------------------------------------
// Causal flash attention with TF32 tensor cores.
// Block: 64 q-rows for one (b,h); 128 threads = 4 warps (16 q-rows each).
// KV tiles of 32. QK^T and PV both via m16n8k8 TF32 mma.
// ---------------------------------------------------------------------------
__global__ __launch_bounds__(128) void flash_attn_tc(
    const float* __restrict__ q, const float* __restrict__ k,
    const float* __restrict__ v, float* __restrict__ o) {
    __shared__ uint32_t Qs[64][68];
    __shared__ uint32_t Ks[32][68];
    __shared__ uint32_t Vs[32][68];
    __shared__ uint32_t Ps[64][36];

    const int t    = threadIdx.x;
    const int lane = t & 31;
    const int warp = t >> 5;
    const int gid  = lane >> 2;  // 0..7
    const int tg   = lane & 3;   // 0..3

    const int q0 = blockIdx.x * 64;
    const int bh = blockIdx.y;
    const size_t base = ((size_t)(bh >> 4) * CS * CH + (bh & 15)) * CHD;
    const int rs = CH * CHD;  // 1024

    // Load Q tile (64x64) as TF32
    for (int i = t; i < 64 * 64; i += 128) {
        int r = i >> 6, d = i & 63;
        Qs[r][d] = f2tf32(q[base + (size_t)(q0 + r) * rs + d]);
    }
    __syncthreads();

    // Preload Q a-fragments (persist across all KV tiles)
    uint32_t qa[8][4];
#pragma unroll
    for (int ks = 0; ks < 8; ++ks) {
        qa[ks][0] = Qs[warp * 16 + gid][ks * 8 + tg];
        qa[ks][1] = Qs[warp * 16 + gid + 8][ks * 8 + tg];
        qa[ks][2] = Qs[warp * 16 + gid][ks * 8 + tg + 4];
        qa[ks][3] = Qs[warp * 16 + gid + 8][ks * 8 + tg + 4];
    }

    float oa[8][4];
#pragma unroll
    for (int dt = 0; dt < 8; ++dt)
#pragma unroll
        for (int i = 0; i < 4; ++i) oa[dt][i] = 0.f;

    float m0 = -1e30f, m1 = -1e30f, l0 = 0.f, l1 = 0.f;
    const int qrow0 = q0 + warp * 16 + gid;
    const int qrow1 = qrow0 + 8;

    const int nkt = (q0 >> 5) + 2;
    for (int kt = 0; kt < nkt; ++kt) {
        const int kv0 = kt << 5;
        __syncthreads();  // previous tile's Ks/Vs reads done
        for (int i = t; i < 32 * 64; i += 128) {
            int rr = i >> 6, d = i & 63;
            size_t gi = base + (size_t)(kv0 + rr) * rs + d;
            Ks[rr][d] = f2tf32(k[gi]);
            Vs[rr][d] = f2tf32(v[gi]);
        }
        __syncthreads();

        // ---- scores: S = Q K^T (16x32 per warp) ----
        float sc[4][4];
#pragma unroll
        for (int nt = 0; nt < 4; ++nt)
#pragma unroll
            for (int i = 0; i < 4; ++i) sc[nt][i] = 0.f;

#pragma unroll
        for (int ks = 0; ks < 8; ++ks) {
#pragma unroll
            for (int nt = 0; nt < 4; ++nt) {
                uint32_t b[2];
                b[0] = Ks[nt * 8 + gid][ks * 8 + tg];
                b[1] = Ks[nt * 8 + gid][ks * 8 + tg + 4];
                mma_tf32(sc[nt], qa[ks], b);
            }
        }

        // ---- scale + causal mask ----
        const bool needmask = (kv0 + 31 > q0);
#pragma unroll
        for (int nt = 0; nt < 4; ++nt) {
            const int c0 = kv0 + nt * 8 + 2 * tg;
            const int c1 = c0 + 1;
            sc[nt][0] *= 0.125f;
            sc[nt][1] *= 0.125f;
            sc[nt][2] *= 0.125f;
            sc[nt][3] *= 0.125f;
            if (needmask) {
                if (c0 > qrow0) sc[nt][0] = -1e9f;
                if (c1 > qrow0) sc[nt][1] = -1e9f;
                if (c0 > qrow1) sc[nt][2] = -1e9f;
                if (c1 > qrow1) sc[nt][3] = -1e9f;
            }
        }

        // ---- online softmax (2 rows per thread, quad reductions) ----
        float tm0 = -1e30f, tm1 = -1e30f;
#pragma unroll
        for (int nt = 0; nt < 4; ++nt) {
            tm0 = fmaxf(tm0, fmaxf(sc[nt][0], sc[nt][1]));
            tm1 = fmaxf(tm1, fmaxf(sc[nt][2], sc[nt][3]));
        }
        tm0 = fmaxf(tm0, __shfl_xor_sync(0xffffffffu, tm0, 1));
        tm0 = fmaxf(tm0, __shfl_xor_sync(0xffffffffu, tm0, 2));
        tm1 = fmaxf(tm1, __shfl_xor_sync(0xffffffffu, tm1, 1));
        tm1 = fmaxf(tm1, __shfl_xor_sync(0xffffffffu, tm1, 2));

        const float m0n = fmaxf(m0, tm0);
        const float m1n = fmaxf(m1, tm1);
        const float a0  = __expf(m0 - m0n);
        const float a1  = __expf(m1 - m1n);

        float s0 = 0.f, s1 = 0.f;
#pragma unroll
        for (int nt = 0; nt < 4; ++nt) {
            const float p00 = __expf(sc[nt][0] - m0n);
            const float p01 = __expf(sc[nt][1] - m0n);
            const float p10 = __expf(sc[nt][2] - m1n);
            const float p11 = __expf(sc[nt][3] - m1n);
            s0 += p00 + p01;
            s1 += p10 + p11;
            const int cc = nt * 8 + 2 * tg;
            Ps[warp * 16 + gid][cc]         = f2tf32(p00);
            Ps[warp * 16 + gid][cc + 1]     = f2tf32(p01);
            Ps[warp * 16 + gid + 8][cc]     = f2tf32(p10);
            Ps[warp * 16 + gid + 8][cc + 1] = f2tf32(p11);
        }
        s0 += __shfl_xor_sync(0xffffffffu, s0, 1);
        s0 += __shfl_xor_sync(0xffffffffu, s0, 2);
        s1 += __shfl_xor_sync(0xffffffffu, s1, 1);
        s1 += __shfl_xor_sync(0xffffffffu, s1, 2);

        l0 = l0 * a0 + s0;
        l1 = l1 * a1 + s1;
        m0 = m0n;
        m1 = m1n;

#pragma unroll
        for (int dt = 0; dt < 8; ++dt) {
            oa[dt][0] *= a0;
            oa[dt][1] *= a0;
            oa[dt][2] *= a1;
            oa[dt][3] *= a1;
        }
        __syncwarp();  // Ps rows are warp-private

        // ---- PV: O += P V (16x32 @ 32x64 per warp) ----
#pragma unroll
        for (int ks = 0; ks < 4; ++ks) {
            uint32_t pa[4];
            pa[0] = Ps[warp * 16 + gid][ks * 8 + tg];
            pa[1] = Ps[warp * 16 + gid + 8][ks * 8 + tg];
            pa[2] = Ps[warp * 16 + gid][ks * 8 + tg + 4];
            pa[3] = Ps[warp * 16 + gid + 8][ks * 8 + tg + 4];
#pragma unroll
            for (int dt = 0; dt < 8; ++dt) {
                uint32_t b[2];
                b[0] = Vs[ks * 8 + tg][dt * 8 + gid];
                b[1] = Vs[ks * 8 + tg + 4][dt * 8 + gid];
                mma_tf32(oa[dt], pa, b);
            }
        }
    }

    // ---- epilogue ----
    const float il0 = 1.0f / l0;
    const float il1 = 1.0f / l1;
#pragma unroll
    for (int dt = 0; dt < 8; ++dt) {
        const int cc = dt * 8 + 2 * tg;
        *(float2*)&o[base + (size_t)qrow0 * rs + cc] =
            make_float2(oa[dt][0] * il0, oa[dt][1] * il0);
        *(float2*)&o[base + (size_t)qrow1 * rs + cc] =
            make_float2(oa[dt][2] * il1, oa[dt][3] * il1);
    }
}

// ---------------------------------------------------------------------------
// Launch
// ---------------------------------------------------------------------------
extern "C" void kernel_launch(void* const* d_in, const int* in_sizes, int n_in,
                              void* d_out, int out_size) {
    (void)in_sizes; (void)n_in; (void)out_size;
    const float* Q  = (const float*)d_in[0];
    const float* K  = (const float*)d_in[1];
    const float* V  = (const float*)d_in[2];
    const float* Wq = (const float*)d_in[4];
    const float* Wk = (const float*)d_in[5];
    const float* Wv = (const float*)d_in[6];
    const float* Wo = (const float*)d_in[7];
    float* out = (float*)d_out;

    float *gq, *gk, *gv, *gvals;
    cudaGetSymbolAddress((void**)&gq, g_q);
    cudaGetSymbolAddress((void**)&gk, g_k);
    cudaGetSymbolAddress((void**)&gv, g_v);
    cudaGetSymbolAddress((void**)&gvals, g_vals);

    const int M = CB * CS;               // 4096
    dim3 ggrid(CD / BN, M / BM);         // (8, 32)

    sgemm_tf32<<<ggrid, 256>>>(Q, Wq, gq, M, CD, CD);
    sgemm_tf32<<<ggrid, 256>>>(K, Wk, gk, M, CD, CD);
    sgemm_tf32<<<ggrid, 256>>>(V, Wv, gv, M, CD, CD);

    const int nwarps = CB * CS * CH;     // 65536
    dim3 rgrid(nwarps / 8);
    rope_rms_kernel<<<rgrid, 256>>>(gq);
    rope_rms_kernel<<<rgrid, 256>>>(gk);

    dim3 agrid(CS / 64, CB * CH);        // (32, 32)
    flash_attn_tc<<<agrid, 128>>>(gq, gk, gv, gvals);

    sgemm_tf32<<<ggrid, 256>>>(gvals, Wo, out, M, CD, CD);
}